// round 9
// baseline (speedup 1.0000x reference)
#include <cuda_runtime.h>
#include <float.h>

// Problem constants
#define B      2
#define C      3
#define T      8
#define H      448
#define W      448
#define NKEY   4
#define L      196      // 14*14
#define GH     14
#define R      121      // 11*11
#define NS     500
#define BK     (B*NKEY) // 8
#define OUTHW  128      // s*A

// Device scratch (no allocation allowed; no cross-replay state needed)
__device__ int   g_arg[BK * NS];   // per-sample argmax region (no init required)
__device__ float g_wc[BK][R];      // compacted weights
__device__ int   g_off[BK][R];     // compacted x element offsets
__device__ int   g_nnz[BK];

// ---------------------------------------------------------------------------
// Kernel 1: fused score-norm + perturbed top-1 argmax.
// grid = (63, 8), block = 256 (8 warps = 8 samples/block).
// Prologue (3 barriers): 4x4 window-mean of the 14x14 scores, shuffle min/max,
// normalize into smem. Then one warp per sample argmaxes 121 perturbed scores.
// Writes per-sample argmax -> no atomics, no global init, deterministic.
// ---------------------------------------------------------------------------
__global__ void argmax_kernel(const float* __restrict__ score,
                              const float* __restrict__ noise,
                              const float* __restrict__ sigma_p)
{
    const int bk   = blockIdx.y;
    const int tid  = threadIdx.x;
    const int lane = tid & 31;
    const int wrp  = tid >> 5;

    __shared__ float sc[R];
    __shared__ float wmin[4], wmax[4];
    __shared__ float lo_s, inv_s;

    // 4x4 window mean (row-major order, /16) — threads 0..120 only
    float v = 0.f;
    if (tid < R) {
        const int ri = tid / 11;
        const int rj = tid % 11;
        const float* sp = score + bk * L;
        #pragma unroll
        for (int ki = 0; ki < 4; ki++)
            #pragma unroll
            for (int kj = 0; kj < 4; kj++)
                v += sp[(ri + ki) * GH + (rj + kj)];
        v *= (1.f / 16.f);
    }

    // block min/max over 121 values (warps 0-3 hold them)
    if (wrp < 4) {
        float mn = (tid < R) ? v : FLT_MAX;
        float mx = (tid < R) ? v : -FLT_MAX;
        #pragma unroll
        for (int o = 16; o > 0; o >>= 1) {
            mn = fminf(mn, __shfl_down_sync(0xffffffffu, mn, o));
            mx = fmaxf(mx, __shfl_down_sync(0xffffffffu, mx, o));
        }
        if (lane == 0) { wmin[wrp] = mn; wmax[wrp] = mx; }
    }
    __syncthreads();
    if (tid == 0) {
        float lo = fminf(fminf(wmin[0], wmin[1]), fminf(wmin[2], wmin[3]));
        float hi = fmaxf(fmaxf(wmax[0], wmax[1]), fmaxf(wmax[2], wmax[3]));
        lo_s  = lo;
        inv_s = 1.f / (hi - lo + 1e-5f);
    }
    __syncthreads();
    if (tid < R) sc[tid] = (v - lo_s) * inv_s;
    __syncthreads();

    // One warp per sample
    const int n = blockIdx.x * 8 + wrp;
    if (n >= NS) return;

    const float sigma = sigma_p[0];
    const float* nn = noise + ((size_t)bk * NS + n) * R;

    // Warp argmax, first-max / lowest-index tie-break (lax.top_k semantics)
    float best = -FLT_MAX;
    int   bi   = 0;
    #pragma unroll
    for (int j = 0; j < 4; j++) {
        int r = lane + 32 * j;
        if (r < R) {
            float p = fmaf(nn[r], sigma, sc[r]);
            if (p > best) { best = p; bi = r; }
        }
    }
    #pragma unroll
    for (int o = 16; o > 0; o >>= 1) {
        float v2 = __shfl_down_sync(0xffffffffu, best, o);
        int   i2 = __shfl_down_sync(0xffffffffu, bi,   o);
        if (v2 > best || (v2 == best && i2 < bi)) { best = v2; bi = i2; }
    }
    if (lane == 0) g_arg[bk * NS + n] = bi;
}

// ---------------------------------------------------------------------------
// Kernel 2: histogram of 500 argmax indices + ordered compaction. 8 blocks.
// Integer smem atomics (order-independent) + serial compaction => deterministic.
// ---------------------------------------------------------------------------
__global__ void compact_kernel()
{
    const int bk  = blockIdx.x;
    const int tid = threadIdx.x;

    __shared__ int cnt[R];
    if (tid < R) cnt[tid] = 0;
    __syncthreads();

    for (int n = tid; n < NS; n += 128)
        atomicAdd(&cnt[g_arg[bk * NS + n]], 1);
    __syncthreads();

    if (tid == 0) {
        int nz = 0;
        for (int r = 0; r < R; r++) {
            int c = cnt[r];
            if (c > 0) {
                g_wc[bk][nz]  = (float)c * (1.f / (float)NS);
                g_off[bk][nz] = (r / 11) * 32 * W + (r % 11) * 32;
                nz++;
            }
        }
        g_nnz[bk] = nz;
    }
}

// ---------------------------------------------------------------------------
// Kernel 3: fused gather + weighted sum, float4-vectorized.
// 8 output rows per block (256 threads); thread (sub,lane): row y0+sub,
// cols lane*4..+3. All addresses 16B-aligned (W=448, offsets mult. of 32).
// ---------------------------------------------------------------------------
__global__ void gather_kernel(const float* __restrict__ x,
                              const int*   __restrict__ group_id,
                              float*       __restrict__ out)
{
    const int tid  = threadIdx.x;
    const int sub  = tid >> 5;
    const int lane = tid & 31;

    const int rowbase = blockIdx.x * 8;        // 8 rows share (b,c,t)
    const int rowhi   = rowbase >> 7;          // (b*3+c)*8 + t
    const int y       = (rowbase & (OUTHW - 1)) + sub;
    const int t       = rowhi & 7;
    const int bc      = rowhi >> 3;            // b*3 + c
    const int b       = bc / 3;

    const int bk = b * NKEY + group_id[b * T + t];

    __shared__ float wc[R];
    __shared__ int   off[R];

    const int nnz = g_nnz[bk];
    if (tid < nnz) {
        wc[tid]  = g_wc[bk][tid];
        off[tid] = g_off[bk][tid];
    }
    __syncthreads();

    const size_t xbase = (((size_t)bc * T + t) * H + y) * W + lane * 4;

    float4 acc = make_float4(0.f, 0.f, 0.f, 0.f);
    #pragma unroll 4
    for (int i = 0; i < nnz; i++) {
        const float w = wc[i];
        const float4 v = *reinterpret_cast<const float4*>(x + xbase + off[i]);
        acc.x = fmaf(w, v.x, acc.x);
        acc.y = fmaf(w, v.y, acc.y);
        acc.z = fmaf(w, v.z, acc.z);
        acc.w = fmaf(w, v.w, acc.w);
    }

    *reinterpret_cast<float4*>(out + ((size_t)(rowbase + sub)) * OUTHW + lane * 4) = acc;
}

// ---------------------------------------------------------------------------
// Launch: inputs (metadata order): x, score, noise, sigma, group_id
// ---------------------------------------------------------------------------
extern "C" void kernel_launch(void* const* d_in, const int* in_sizes, int n_in,
                              void* d_out, int out_size)
{
    const float* x        = (const float*)d_in[0];
    const float* score    = (const float*)d_in[1];
    const float* noise    = (const float*)d_in[2];
    const float* sigma    = (const float*)d_in[3];
    const int*   group_id = (const int*)  d_in[4];
    float*       out      = (float*)d_out;

    argmax_kernel<<<dim3(63, BK), 256>>>(score, noise, sigma);
    compact_kernel<<<BK, 128>>>();

    const int nblocks = (B * C * T * OUTHW) / 8;   // 768
    gather_kernel<<<nblocks, 256>>>(x, group_id, out);
}

// round 10
// speedup vs baseline: 1.8291x; 1.8291x over previous
#include <cuda_runtime.h>
#include <float.h>

// Problem constants
#define B      2
#define C      3
#define T      8
#define H      448
#define W      448
#define NKEY   4
#define L      196      // 14*14
#define GH     14
#define R      121      // 11*11
#define NS     500
#define BK     (B*NKEY) // 8
#define OUTHW  128      // s*A

// Device scratch (no allocation allowed)
__device__ float g_scn[BK][R];   // normalized region scores (producer block writes)
__device__ int   g_cnt[BK][R];   // top-1 histogram (zeroed by producer each launch)
__device__ int   g_flag[BK];     // handshake flags: 0 at module load; gather resets
                                 // them each launch, so every replay starts at 0.

// ---------------------------------------------------------------------------
// Kernel 1: fused score-norm + perturbed top-1 argmax (2-node pipeline).
// grid = (63, BK), block = 256 (8 warps = 8 samples/block). Single wave
// guaranteed (504 blocks, >=592 resident) => intra-kernel handshake is safe.
//   block x==0 per key: 4x4 window-mean of 14x14 scores, shuffle min/max,
//     normalize -> g_scn, zero g_cnt, fence, raise g_flag[bk].
//   other blocks: one thread polls g_flag[bk] (L2 atomic + nanosleep).
// Then: one warp per sample argmaxes 121 perturbed scores, atomic histogram.
// ---------------------------------------------------------------------------
__global__ void argmax_kernel(const float* __restrict__ score,
                              const float* __restrict__ noise,
                              const float* __restrict__ sigma_p)
{
    const int bk   = blockIdx.y;
    const int tid  = threadIdx.x;
    const int lane = tid & 31;
    const int wrp  = tid >> 5;

    __shared__ float sc[R];
    __shared__ float wmin[4], wmax[4];
    __shared__ float lo_s, inv_s;

    if (blockIdx.x == 0) {
        // ---- producer: compute normalized scores once per key ----
        float v = 0.f;
        if (tid < R) {
            const int ri = tid / 11;
            const int rj = tid % 11;
            const float* sp = score + bk * L;
            #pragma unroll
            for (int ki = 0; ki < 4; ki++)
                #pragma unroll
                for (int kj = 0; kj < 4; kj++)
                    v += sp[(ri + ki) * GH + (rj + kj)];
            v *= (1.f / 16.f);
        }
        if (wrp < 4) {
            float mn = (tid < R) ? v : FLT_MAX;
            float mx = (tid < R) ? v : -FLT_MAX;
            #pragma unroll
            for (int o = 16; o > 0; o >>= 1) {
                mn = fminf(mn, __shfl_down_sync(0xffffffffu, mn, o));
                mx = fmaxf(mx, __shfl_down_sync(0xffffffffu, mx, o));
            }
            if (lane == 0) { wmin[wrp] = mn; wmax[wrp] = mx; }
        }
        __syncthreads();
        if (tid == 0) {
            float lo = fminf(fminf(wmin[0], wmin[1]), fminf(wmin[2], wmin[3]));
            float hi = fmaxf(fmaxf(wmax[0], wmax[1]), fmaxf(wmax[2], wmax[3]));
            lo_s  = lo;
            inv_s = 1.f / (hi - lo + 1e-5f);
        }
        __syncthreads();
        if (tid < R) {
            float nv = (v - lo_s) * inv_s;
            sc[tid] = nv;
            g_scn[bk][tid] = nv;
            g_cnt[bk][tid] = 0;
        }
        __syncthreads();
        if (tid == 0) {
            __threadfence();                       // release g_scn / g_cnt
            atomicExch(&g_flag[bk], 1);
        }
    } else {
        // ---- consumer: wait for producer, then load normalized scores ----
        if (tid == 0) {
            while (atomicAdd(&g_flag[bk], 0) == 0) __nanosleep(32);
        }
        __syncthreads();
        if (tid < R) sc[tid] = __ldcg(&g_scn[bk][tid]);   // bypass L1 (fresh)
        __syncthreads();
    }

    // ---- one warp per sample ----
    const int n = blockIdx.x * 8 + wrp;
    if (n >= NS) return;

    const float sigma = sigma_p[0];
    const float* nn = noise + ((size_t)bk * NS + n) * R;

    // Warp argmax, first-max / lowest-index tie-break (lax.top_k semantics)
    float best = -FLT_MAX;
    int   bi   = 0;
    #pragma unroll
    for (int j = 0; j < 4; j++) {
        int r = lane + 32 * j;
        if (r < R) {
            float p = fmaf(nn[r], sigma, sc[r]);
            if (p > best) { best = p; bi = r; }
        }
    }
    #pragma unroll
    for (int o = 16; o > 0; o >>= 1) {
        float v2 = __shfl_down_sync(0xffffffffu, best, o);
        int   i2 = __shfl_down_sync(0xffffffffu, bi,   o);
        if (v2 > best || (v2 == best && i2 < bi)) { best = v2; bi = i2; }
    }
    if (lane == 0) atomicAdd(&g_cnt[bk][bi], 1);           // order-independent
}

// ---------------------------------------------------------------------------
// Kernel 2: fused gather + weighted sum, float4-vectorized, with inline
// order-preserving ballot compaction of the count histogram (R8-proven).
// 4 output rows per block; thread (sub,lane): row y0+sub, cols lane*4..+3.
// Also resets the handshake flags for the next launch (graph-ordered).
// ---------------------------------------------------------------------------
__global__ void gather_kernel(const float* __restrict__ x,
                              const int*   __restrict__ group_id,
                              float*       __restrict__ out)
{
    const int tid  = threadIdx.x;
    const int sub  = tid >> 5;
    const int lane = tid & 31;

    // flag reset for next launch: exactly one block, ordering irrelevant here
    if (blockIdx.x == 0 && tid < BK) g_flag[tid] = 0;

    const int rowbase = blockIdx.x * 4;        // 4 rows share (b,c,t)
    const int rowhi   = rowbase >> 7;          // (b*3+c)*8 + t
    const int y       = (rowbase & (OUTHW - 1)) + sub;
    const int t       = rowhi & 7;
    const int bc      = rowhi >> 3;            // b*3 + c
    const int b       = bc / 3;

    const int bk = b * NKEY + group_id[b * T + t];

    __shared__ float wc[R];
    __shared__ int   off[R];
    __shared__ int   wbase[4];
    __shared__ int   nnz_s;

    // Ballot compaction: region order preserved => deterministic
    int  cnt = (tid < R) ? g_cnt[bk][tid] : 0;
    bool p   = (cnt > 0);
    unsigned m = __ballot_sync(0xffffffffu, p);
    int within = __popc(m & ((1u << lane) - 1u));
    if (lane == 0) wbase[sub] = __popc(m);
    __syncthreads();
    if (tid == 0) {
        int s = 0;
        #pragma unroll
        for (int w2 = 0; w2 < 4; w2++) { int tt = wbase[w2]; wbase[w2] = s; s += tt; }
        nnz_s = s;
    }
    __syncthreads();
    if (p) {
        int pos = wbase[sub] + within;
        wc[pos]  = (float)cnt * (1.f / (float)NS);
        off[pos] = (tid / 11) * 32 * W + (tid % 11) * 32;
    }
    __syncthreads();

    const int nnz = nnz_s;
    const size_t xbase = (((size_t)bc * T + t) * H + y) * W + lane * 4;

    float4 acc = make_float4(0.f, 0.f, 0.f, 0.f);
    #pragma unroll 4
    for (int i = 0; i < nnz; i++) {
        const float w = wc[i];
        const float4 v = *reinterpret_cast<const float4*>(x + xbase + off[i]);
        acc.x = fmaf(w, v.x, acc.x);
        acc.y = fmaf(w, v.y, acc.y);
        acc.z = fmaf(w, v.z, acc.z);
        acc.w = fmaf(w, v.w, acc.w);
    }

    *reinterpret_cast<float4*>(out + ((size_t)(rowbase + sub)) * OUTHW + lane * 4) = acc;
}

// ---------------------------------------------------------------------------
// Launch: inputs (metadata order): x, score, noise, sigma, group_id
// Two graph nodes total.
// ---------------------------------------------------------------------------
extern "C" void kernel_launch(void* const* d_in, const int* in_sizes, int n_in,
                              void* d_out, int out_size)
{
    const float* x        = (const float*)d_in[0];
    const float* score    = (const float*)d_in[1];
    const float* noise    = (const float*)d_in[2];
    const float* sigma    = (const float*)d_in[3];
    const int*   group_id = (const int*)  d_in[4];
    float*       out      = (float*)d_out;

    argmax_kernel<<<dim3(63, BK), 256>>>(score, noise, sigma);

    const int nblocks = (B * C * T * OUTHW) / 4;   // 1536
    gather_kernel<<<nblocks, 128>>>(x, group_id, out);
}